// round 3
// baseline (speedup 1.0000x reference)
#include <cuda_runtime.h>
#include <math.h>

#define B_  8
#define T_  8192
#define F_  64
#define M_  128          // omega rows
#define MM2 256          // feature dim = 2*M
#define D_  64
#define DP_ 65           // D + 1 (normalizer column)
#define KV_CHUNKS 32
#define KV_ROWS (T_ / KV_CHUNKS)   // 256 s-rows per kv block

constexpr float kEPS   = 1e-9f;
constexpr float kSCALE = 0.0625f;  // 1/sqrt(2*128) = 1/16

// ---------------- device scratch (static, allocation-free) ----------------
__device__ float g_phiq[(size_t)B_ * T_ * MM2];                 // 67.1 MB
__device__ float g_phik[(size_t)B_ * T_ * MM2];                 // 67.1 MB
__device__ float g_kvp [(size_t)KV_CHUNKS * B_ * MM2 * DP_];    // 17.0 MB
__device__ float g_kv  [(size_t)B_ * MM2 * DP_];                // 0.53 MB

// ======================= Stage 1: phi features =======================
// grid (T/32, B), block 256. Computes phi[b, t0..t0+31, 0..255].
// Thread (tx = tid&31 -> m quad = 4*tx, ty = tid>>5 -> rows ty*4..ty*4+3).
__global__ void __launch_bounds__(256) phi_kernel(const float* __restrict__ x,
                                                  const float* __restrict__ omega,
                                                  int which)
{
    __shared__ float xs[32 * 64];      // 8 KB, input tile
    __shared__ float wT[64 * 132];     // 33.8 KB, omega^T padded (rows 528B, 16B aligned)
    __shared__ float ss[32];

    float* phi = which ? g_phik : g_phiq;
    const int b   = blockIdx.y;
    const int t0  = blockIdx.x * 32;
    const int tid = threadIdx.x;

    // load x tile: coalesced float4
    {
        const float4* xg = reinterpret_cast<const float4*>(x + ((size_t)b * T_ + t0) * F_);
        float4* xs4 = reinterpret_cast<float4*>(xs);
        xs4[tid]       = xg[tid];
        xs4[tid + 256] = xg[tid + 256];
    }
    // load omega transposed: global coalesced, smem 4-way write conflict (one-time)
    #pragma unroll
    for (int i = 0; i < 32; i++) {
        int idx = tid + 256 * i;               // 8192 floats
        wT[(idx & 63) * 132 + (idx >> 6)] = omega[idx];
    }
    __syncthreads();

    // ss[r] = 0.5 * sum_f x[r][f]^2  — one warp per 4 rows, conflict-free lanes
    {
        int w = tid >> 5, l = tid & 31;
        #pragma unroll
        for (int j = 0; j < 4; j++) {
            int r = w * 4 + j;
            float v0 = xs[r * 64 + l];
            float v1 = xs[r * 64 + 32 + l];
            float p = v0 * v0 + v1 * v1;
            p += __shfl_xor_sync(0xffffffffu, p, 16);
            p += __shfl_xor_sync(0xffffffffu, p, 8);
            p += __shfl_xor_sync(0xffffffffu, p, 4);
            p += __shfl_xor_sync(0xffffffffu, p, 2);
            p += __shfl_xor_sync(0xffffffffu, p, 1);
            if (l == 0) ss[r] = 0.5f * p;
        }
    }
    __syncthreads();

    const int tx = tid & 31;   // m quad
    const int ty = tid >> 5;   // row group

    float acc[4][4];
    #pragma unroll
    for (int j = 0; j < 4; j++)
        #pragma unroll
        for (int c = 0; c < 4; c++) acc[j][c] = 0.f;

    // xw = x . omega^T : 8 LDS.128 per 64 FFMA
    #pragma unroll
    for (int f0 = 0; f0 < 64; f0 += 4) {
        float4 w0 = *reinterpret_cast<const float4*>(&wT[(f0 + 0) * 132 + tx * 4]);
        float4 w1 = *reinterpret_cast<const float4*>(&wT[(f0 + 1) * 132 + tx * 4]);
        float4 w2 = *reinterpret_cast<const float4*>(&wT[(f0 + 2) * 132 + tx * 4]);
        float4 w3 = *reinterpret_cast<const float4*>(&wT[(f0 + 3) * 132 + tx * 4]);
        #pragma unroll
        for (int j = 0; j < 4; j++) {
            float4 xv = *reinterpret_cast<const float4*>(&xs[(ty * 4 + j) * 64 + f0]);
            acc[j][0] += xv.x * w0.x + xv.y * w1.x + xv.z * w2.x + xv.w * w3.x;
            acc[j][1] += xv.x * w0.y + xv.y * w1.y + xv.z * w2.y + xv.w * w3.y;
            acc[j][2] += xv.x * w0.z + xv.y * w1.z + xv.z * w2.z + xv.w * w3.z;
            acc[j][3] += xv.x * w0.w + xv.y * w1.w + xv.z * w2.w + xv.w * w3.w;
        }
    }

    // phi = (exp(+-xw - ss) + eps) / 16 ; coalesced float4 stores
    #pragma unroll
    for (int j = 0; j < 4; j++) {
        int r = ty * 4 + j;
        float s = ss[r];
        float4 p1, p2;
        p1.x = (__expf(acc[j][0] - s) + kEPS) * kSCALE;
        p1.y = (__expf(acc[j][1] - s) + kEPS) * kSCALE;
        p1.z = (__expf(acc[j][2] - s) + kEPS) * kSCALE;
        p1.w = (__expf(acc[j][3] - s) + kEPS) * kSCALE;
        p2.x = (__expf(-acc[j][0] - s) + kEPS) * kSCALE;
        p2.y = (__expf(-acc[j][1] - s) + kEPS) * kSCALE;
        p2.z = (__expf(-acc[j][2] - s) + kEPS) * kSCALE;
        p2.w = (__expf(-acc[j][3] - s) + kEPS) * kSCALE;
        float* dst = phi + ((size_t)b * T_ + t0 + r) * MM2 + tx * 4;
        *reinterpret_cast<float4*>(dst)      = p1;
        *reinterpret_cast<float4*>(dst + M_) = p2;
    }
}

// ======================= Stage 2: kv partials =======================
// grid (KV_CHUNKS, B), block 256. Thread owns feature m = tid, 65 accumulators.
// Writes deterministic partials to g_kvp (no atomics).
__global__ void __launch_bounds__(256) kv_kernel(const float* __restrict__ value)
{
    __shared__ float vs[16][68];   // staged V rows; broadcast reads

    const int b   = blockIdx.y;
    const int cx  = blockIdx.x;
    const int s0  = cx * KV_ROWS;
    const int tid = threadIdx.x;

    float acc[DP_];
    #pragma unroll
    for (int d = 0; d < DP_; d++) acc[d] = 0.f;

    const float*  phik = g_phik + ((size_t)b * T_ + s0) * MM2 + tid;   // coalesced
    const float4* vg   = reinterpret_cast<const float4*>(value + ((size_t)b * T_ + s0) * D_);
    const int lr = tid >> 4, lc = tid & 15;

    for (int sb = 0; sb < KV_ROWS; sb += 16) {
        __syncthreads();
        {   // stage 16 V rows (16x64 floats = 256 float4, one per thread)
            float4 v = vg[(sb + lr) * 16 + lc];
            *reinterpret_cast<float4*>(&vs[lr][lc * 4]) = v;
        }
        __syncthreads();
        #pragma unroll
        for (int j = 0; j < 16; j++) {
            float ph = phik[(size_t)(sb + j) * MM2];   // batched LDG (MLP 16)
            #pragma unroll
            for (int d4 = 0; d4 < 16; d4++) {
                float4 vv = *reinterpret_cast<const float4*>(&vs[j][d4 * 4]);
                acc[d4 * 4 + 0] += ph * vv.x;
                acc[d4 * 4 + 1] += ph * vv.y;
                acc[d4 * 4 + 2] += ph * vv.z;
                acc[d4 * 4 + 3] += ph * vv.w;
            }
            acc[64] += ph;   // ones column: normalizer = sum(phi)
        }
    }

    float* dst = g_kvp + (((size_t)cx * B_ + b) * MM2 + tid) * DP_;
    #pragma unroll
    for (int d = 0; d < DP_; d++) dst[d] = acc[d];
}

// ======================= Stage 2b: reduce partials =======================
__global__ void reduce_kv()
{
    int i = blockIdx.x * blockDim.x + threadIdx.x;
    if (i < B_ * MM2 * DP_) {
        float s = 0.f;
        #pragma unroll
        for (int c = 0; c < KV_CHUNKS; c++)
            s += g_kvp[(size_t)c * (B_ * MM2 * DP_) + i];
        g_kv[i] = s;
    }
}

// ======================= Stage 3: qkv + normalize =======================
// grid (T/64, B), block 256, dynamic smem 136 KB.
// Thread (tt = tid>>2 row, p = tid&3 owns 16 cols; p==3 also owns normalizer).
#define QKV_SMEM ((256 * 68 + 64 * 260 + 64) * 4)

__global__ void __launch_bounds__(256) qkv_kernel(float* __restrict__ out)
{
    extern __shared__ float sm[];
    float* kvs  = sm;               // [256][68] padded
    float* phis = sm + 256 * 68;    // [64][260] padded (8 distinct banks/warp)
    float* norm = phis + 64 * 260;  // [64]

    const int b   = blockIdx.y;
    const int t0  = blockIdx.x * 64;
    const int tid = threadIdx.x;

    // load kv matrix for this batch
    const float* kvg = g_kv + (size_t)b * MM2 * DP_;
    for (int i = tid; i < MM2 * DP_; i += 256) {
        int r = i / DP_;
        int d = i - r * DP_;
        kvs[r * 68 + d] = kvg[i];
    }
    // load phi_q tile (64 x 256), coalesced float4
    const float4* pg = reinterpret_cast<const float4*>(g_phiq + ((size_t)b * T_ + t0) * MM2);
    #pragma unroll
    for (int i = 0; i < 16; i++) {
        int idx = tid + 256 * i;           // 4096 float4
        int r = idx >> 6, c4 = idx & 63;
        *reinterpret_cast<float4*>(&phis[r * 260 + c4 * 4]) = pg[idx];
    }
    __syncthreads();

    const int tt  = tid >> 2;
    const int p   = tid & 3;
    const int dof = p * 16;
    const float* ph = &phis[tt * 260];

    float4 a0 = make_float4(0.f, 0.f, 0.f, 0.f), a1 = a0, a2 = a0, a3 = a0;
    float anorm = 0.f;

    #pragma unroll 8
    for (int m = 0; m < MM2; m++) {
        float f = ph[m];
        const float* kr = &kvs[m * 68 + dof];
        float4 k0 = *reinterpret_cast<const float4*>(kr);
        float4 k1 = *reinterpret_cast<const float4*>(kr + 4);
        float4 k2 = *reinterpret_cast<const float4*>(kr + 8);
        float4 k3 = *reinterpret_cast<const float4*>(kr + 12);
        a0.x += f * k0.x; a0.y += f * k0.y; a0.z += f * k0.z; a0.w += f * k0.w;
        a1.x += f * k1.x; a1.y += f * k1.y; a1.z += f * k1.z; a1.w += f * k1.w;
        a2.x += f * k2.x; a2.y += f * k2.y; a2.z += f * k2.z; a2.w += f * k2.w;
        a3.x += f * k3.x; a3.y += f * k3.y; a3.z += f * k3.z; a3.w += f * k3.w;
        if (p == 3) anorm += f * kvs[m * 68 + 64];
    }

    if (p == 3) norm[tt] = anorm;
    __syncthreads();

    float inv = 1.0f / norm[tt];
    a0.x *= inv; a0.y *= inv; a0.z *= inv; a0.w *= inv;
    a1.x *= inv; a1.y *= inv; a1.z *= inv; a1.w *= inv;
    a2.x *= inv; a2.y *= inv; a2.z *= inv; a2.w *= inv;
    a3.x *= inv; a3.y *= inv; a3.z *= inv; a3.w *= inv;

    float4* og = reinterpret_cast<float4*>(out + ((size_t)b * T_ + t0 + tt) * D_ + dof);
    og[0] = a0; og[1] = a1; og[2] = a2; og[3] = a3;
}

// ======================= launch =======================
extern "C" void kernel_launch(void* const* d_in, const int* in_sizes, int n_in,
                              void* d_out, int out_size)
{
    const float* query = (const float*)d_in[0];
    const float* value = (const float*)d_in[1];
    const float* key   = (const float*)d_in[2];
    const float* omega = (const float*)d_in[3];
    float* out = (float*)d_out;

    cudaFuncSetAttribute(qkv_kernel, cudaFuncAttributeMaxDynamicSharedMemorySize, QKV_SMEM);

    dim3 gphi(T_ / 32, B_);
    phi_kernel<<<gphi, 256>>>(query, omega, 0);
    phi_kernel<<<gphi, 256>>>(key,   omega, 1);

    dim3 gkv(KV_CHUNKS, B_);
    kv_kernel<<<gkv, 256>>>(value);
    reduce_kv<<<(B_ * MM2 * DP_ + 255) / 256, 256>>>();

    dim3 gq(T_ / 64, B_);
    qkv_kernel<<<gq, 256, QKV_SMEM>>>(out);
}